// round 1
// baseline (speedup 1.0000x reference)
#include <cuda_runtime.h>

// LinearSelfAttention: out = H + ((P G Q - u v^T) H) / n
//   G = H H^T (257x257 per batch), u = P h_n, v^T = h_n^T Q, h_n = H[:, :, -1]
// H: (16, 257, 2049) f32, P,Q: (257,257) f32.

#define RDIM 257
#define NCOL 2049
#define NBAT 16
#define INV_N (1.0f / 2048.0f)

__device__ float g_G[NBAT][RDIM * RDIM];
__device__ float g_T[NBAT][RDIM * RDIM];
__device__ float g_M[NBAT][RDIM * RDIM];
__device__ float g_u[NBAT][RDIM];
__device__ float g_v[NBAT][RDIM];

// ---------------------------------------------------------------------------
// Kernel 1: G_b = H_b @ H_b^T   (NT gemm: both operands K-contiguous)
// 64x64 tile, BK=16, 256 threads, 4x4 per thread.
// ---------------------------------------------------------------------------
__global__ void __launch_bounds__(256) k_syrk(const float* __restrict__ H) {
    const int b = blockIdx.z;
    const float* __restrict__ Hb = H + (size_t)b * RDIM * NCOL;
    const int i0 = blockIdx.y * 64;
    const int j0 = blockIdx.x * 64;

    __shared__ float As[16][65];
    __shared__ float Bs[16][65];

    const int tid = threadIdx.x;
    const int tx = tid & 15;
    const int ty = tid >> 4;

    float acc[4][4] = {};

    for (int k0 = 0; k0 < NCOL; k0 += 16) {
#pragma unroll
        for (int l = 0; l < 4; l++) {
            int e = tid + l * 256;
            int m = e >> 4;
            int kk = e & 15;
            int k = k0 + kk;
            int ra = i0 + m;
            int rb = j0 + m;
            As[kk][m] = (ra < RDIM && k < NCOL) ? Hb[(size_t)ra * NCOL + k] : 0.0f;
            Bs[kk][m] = (rb < RDIM && k < NCOL) ? Hb[(size_t)rb * NCOL + k] : 0.0f;
        }
        __syncthreads();
#pragma unroll
        for (int kk = 0; kk < 16; kk++) {
            float a[4], bb[4];
#pragma unroll
            for (int i = 0; i < 4; i++) a[i] = As[kk][ty * 4 + i];
#pragma unroll
            for (int j = 0; j < 4; j++) bb[j] = Bs[kk][tx * 4 + j];
#pragma unroll
            for (int i = 0; i < 4; i++)
#pragma unroll
                for (int j = 0; j < 4; j++) acc[i][j] += a[i] * bb[j];
        }
        __syncthreads();
    }

    float* __restrict__ Gb = g_G[b];
#pragma unroll
    for (int i = 0; i < 4; i++) {
        int row = i0 + ty * 4 + i;
        if (row >= RDIM) continue;
#pragma unroll
        for (int j = 0; j < 4; j++) {
            int col = j0 + tx * 4 + j;
            if (col < RDIM) Gb[row * RDIM + col] = acc[i][j];
        }
    }
}

// ---------------------------------------------------------------------------
// Kernel 2: u_b = P h_n,  v_b = Q^T h_n  (tiny)
// ---------------------------------------------------------------------------
__global__ void k_uv(const float* __restrict__ H, const float* __restrict__ P,
                     const float* __restrict__ Q) {
    const int b = blockIdx.x;
    const float* __restrict__ Hb = H + (size_t)b * RDIM * NCOL;
    __shared__ float hn[RDIM];
    for (int e = threadIdx.x; e < RDIM; e += blockDim.x)
        hn[e] = Hb[(size_t)e * NCOL + (NCOL - 1)];
    __syncthreads();
    for (int i = threadIdx.x; i < RDIM; i += blockDim.x) {
        float su = 0.0f, sv = 0.0f;
        for (int e = 0; e < RDIM; e++) {
            su += P[i * RDIM + e] * hn[e];
            sv += hn[e] * Q[e * RDIM + i];
        }
        g_u[b][i] = su;
        g_v[b][i] = sv;
    }
}

// ---------------------------------------------------------------------------
// Kernel 3: T_b = G_b @ Q   (NN gemm, 257x257x257)
// ---------------------------------------------------------------------------
__global__ void __launch_bounds__(256) k_gq(const float* __restrict__ Q) {
    const int b = blockIdx.z;
    const float* __restrict__ A = g_G[b];
    const int i0 = blockIdx.y * 64;
    const int j0 = blockIdx.x * 64;

    __shared__ float As[16][65];
    __shared__ float Bs[16][64];

    const int tid = threadIdx.x;
    const int tx = tid & 15;
    const int ty = tid >> 4;

    float acc[4][4] = {};

    for (int k0 = 0; k0 < RDIM; k0 += 16) {
#pragma unroll
        for (int l = 0; l < 4; l++) {
            int e = tid + l * 256;
            // A tile: As[kk][m] = A[(i0+m), k0+kk]
            int m = e >> 4, kk = e & 15;
            int row = i0 + m, k = k0 + kk;
            As[kk][m] = (row < RDIM && k < RDIM) ? A[row * RDIM + k] : 0.0f;
            // B tile: Bs[kk2][nn] = Q[(k0+kk2), j0+nn]
            int kk2 = e >> 6, nn = e & 63;
            int kb = k0 + kk2, col = j0 + nn;
            Bs[kk2][nn] = (kb < RDIM && col < RDIM) ? Q[kb * RDIM + col] : 0.0f;
        }
        __syncthreads();
#pragma unroll
        for (int kk = 0; kk < 16; kk++) {
            float a[4], bb[4];
#pragma unroll
            for (int i = 0; i < 4; i++) a[i] = As[kk][ty * 4 + i];
#pragma unroll
            for (int j = 0; j < 4; j++) bb[j] = Bs[kk][tx * 4 + j];
#pragma unroll
            for (int i = 0; i < 4; i++)
#pragma unroll
                for (int j = 0; j < 4; j++) acc[i][j] += a[i] * bb[j];
        }
        __syncthreads();
    }

    float* __restrict__ Tb = g_T[b];
#pragma unroll
    for (int i = 0; i < 4; i++) {
        int row = i0 + ty * 4 + i;
        if (row >= RDIM) continue;
#pragma unroll
        for (int j = 0; j < 4; j++) {
            int col = j0 + tx * 4 + j;
            if (col < RDIM) Tb[row * RDIM + col] = acc[i][j];
        }
    }
}

// ---------------------------------------------------------------------------
// Kernel 4: M_b = P @ T_b - u_b v_b^T
// ---------------------------------------------------------------------------
__global__ void __launch_bounds__(256) k_pt(const float* __restrict__ P) {
    const int b = blockIdx.z;
    const float* __restrict__ Bm = g_T[b];
    const int i0 = blockIdx.y * 64;
    const int j0 = blockIdx.x * 64;

    __shared__ float As[16][65];
    __shared__ float Bs[16][64];

    const int tid = threadIdx.x;
    const int tx = tid & 15;
    const int ty = tid >> 4;

    float acc[4][4] = {};

    for (int k0 = 0; k0 < RDIM; k0 += 16) {
#pragma unroll
        for (int l = 0; l < 4; l++) {
            int e = tid + l * 256;
            int m = e >> 4, kk = e & 15;
            int row = i0 + m, k = k0 + kk;
            As[kk][m] = (row < RDIM && k < RDIM) ? P[row * RDIM + k] : 0.0f;
            int kk2 = e >> 6, nn = e & 63;
            int kb = k0 + kk2, col = j0 + nn;
            Bs[kk2][nn] = (kb < RDIM && col < RDIM) ? Bm[kb * RDIM + col] : 0.0f;
        }
        __syncthreads();
#pragma unroll
        for (int kk = 0; kk < 16; kk++) {
            float a[4], bb[4];
#pragma unroll
            for (int i = 0; i < 4; i++) a[i] = As[kk][ty * 4 + i];
#pragma unroll
            for (int j = 0; j < 4; j++) bb[j] = Bs[kk][tx * 4 + j];
#pragma unroll
            for (int i = 0; i < 4; i++)
#pragma unroll
                for (int j = 0; j < 4; j++) acc[i][j] += a[i] * bb[j];
        }
        __syncthreads();
    }

    float* __restrict__ Mb = g_M[b];
#pragma unroll
    for (int i = 0; i < 4; i++) {
        int row = i0 + ty * 4 + i;
        if (row >= RDIM) continue;
        float ur = g_u[b][row];
#pragma unroll
        for (int j = 0; j < 4; j++) {
            int col = j0 + tx * 4 + j;
            if (col < RDIM) Mb[row * RDIM + col] = acc[i][j] - ur * g_v[b][col];
        }
    }
}

// ---------------------------------------------------------------------------
// Kernel 5: out_b = H_b + (M_b @ H_b) / n   (NN gemm, 257x2049x257)
// ---------------------------------------------------------------------------
__global__ void __launch_bounds__(256) k_out(const float* __restrict__ H,
                                             float* __restrict__ out) {
    const int b = blockIdx.z;
    const float* __restrict__ A = g_M[b];
    const float* __restrict__ Hb = H + (size_t)b * RDIM * NCOL;
    float* __restrict__ Ob = out + (size_t)b * RDIM * NCOL;
    const int i0 = blockIdx.y * 64;
    const int j0 = blockIdx.x * 64;

    __shared__ float As[16][65];
    __shared__ float Bs[16][64];

    const int tid = threadIdx.x;
    const int tx = tid & 15;
    const int ty = tid >> 4;

    float acc[4][4] = {};

    for (int k0 = 0; k0 < RDIM; k0 += 16) {
#pragma unroll
        for (int l = 0; l < 4; l++) {
            int e = tid + l * 256;
            int m = e >> 4, kk = e & 15;
            int row = i0 + m, k = k0 + kk;
            As[kk][m] = (row < RDIM && k < RDIM) ? A[row * RDIM + k] : 0.0f;
            int kk2 = e >> 6, nn = e & 63;
            int kb = k0 + kk2, col = j0 + nn;
            Bs[kk2][nn] =
                (kb < RDIM && col < NCOL) ? Hb[(size_t)kb * NCOL + col] : 0.0f;
        }
        __syncthreads();
#pragma unroll
        for (int kk = 0; kk < 16; kk++) {
            float a[4], bb[4];
#pragma unroll
            for (int i = 0; i < 4; i++) a[i] = As[kk][ty * 4 + i];
#pragma unroll
            for (int j = 0; j < 4; j++) bb[j] = Bs[kk][tx * 4 + j];
#pragma unroll
            for (int i = 0; i < 4; i++)
#pragma unroll
                for (int j = 0; j < 4; j++) acc[i][j] += a[i] * bb[j];
        }
        __syncthreads();
    }

#pragma unroll
    for (int i = 0; i < 4; i++) {
        int row = i0 + ty * 4 + i;
        if (row >= RDIM) continue;
#pragma unroll
        for (int j = 0; j < 4; j++) {
            int col = j0 + tx * 4 + j;
            if (col < NCOL) {
                size_t idx = (size_t)row * NCOL + col;
                Ob[idx] = Hb[idx] + acc[i][j] * INV_N;
            }
        }
    }
}

// ---------------------------------------------------------------------------
extern "C" void kernel_launch(void* const* d_in, const int* in_sizes, int n_in,
                              void* d_out, int out_size) {
    const float* H = (const float*)d_in[0];
    const float* P = (const float*)d_in[1];
    const float* Q = (const float*)d_in[2];
    float* out = (float*)d_out;

    dim3 blk(256);
    // G_b = H H^T : tiles 5x5, 16 batches
    k_syrk<<<dim3(5, 5, NBAT), blk>>>(H);
    // u, v
    k_uv<<<NBAT, 288>>>(H, P, Q);
    // T = G Q
    k_gq<<<dim3(5, 5, NBAT), blk>>>(Q);
    // M = P T - u v^T
    k_pt<<<dim3(5, 5, NBAT), blk>>>(P);
    // out = H + (M H)/n : tiles 33x5, 16 batches
    k_out<<<dim3(33, 5, NBAT), blk>>>(H, out);
}

// round 3
// speedup vs baseline: 1.5238x; 1.5238x over previous
#include <cuda_runtime.h>
#include <cstdint>

// LinearSelfAttention via mma.sync tf32 GEMMs (tcgen05 unavailable: harness
// PTX target is sm_103 without the 'a' feature suffix).
// out = H + ((P G Q - u v^T) H) / n,  G = H H^T, u = P h_n, v = Q^T h_n.

#define RDIM 257
#define NCOL 2049
#define NBAT 16
#define INV_N (1.0f / 2048.0f)

__device__ float g_G[NBAT][RDIM * RDIM];
__device__ float g_T[NBAT][RDIM * RDIM];
__device__ float g_W[NBAT][RDIM * RDIM];
__device__ float g_u[NBAT][RDIM];
__device__ float g_v[NBAT][RDIM];

// ---------------------------------------------------------------------------
__device__ __forceinline__ uint32_t smem_u32(const void* p) {
    uint32_t a;
    asm("{ .reg .u64 t; cvta.to.shared.u64 t, %1; cvt.u32.u64 %0, t; }"
        : "=r"(a) : "l"(p));
    return a;
}

__device__ __forceinline__ void cp4(void* s, const void* g) {
    uint32_t sa = smem_u32(s);
    asm volatile("cp.async.ca.shared.global [%0], [%1], 4;"
                 :: "r"(sa), "l"(g) : "memory");
}
#define CP_COMMIT() asm volatile("cp.async.commit_group;" ::: "memory")
#define CP_WAIT0()  asm volatile("cp.async.wait_group 0;" ::: "memory")

// m16n8k8 tf32: D += A * B  (fp32 inputs: HW uses tf32 bits = truncation)
__device__ __forceinline__ void mma8(float* c, const uint32_t* a,
                                     const uint32_t* b) {
    asm volatile(
        "mma.sync.aligned.m16n8k8.row.col.f32.tf32.tf32.f32 "
        "{%0,%1,%2,%3}, {%4,%5,%6,%7}, {%8,%9}, {%0,%1,%2,%3};"
        : "+f"(c[0]), "+f"(c[1]), "+f"(c[2]), "+f"(c[3])
        : "r"(a[0]), "r"(a[1]), "r"(a[2]), "r"(a[3]), "r"(b[0]), "r"(b[1]));
}

// ---------------------------------------------------------------------------
// SMEM tile loaders (cp.async 4B, zero-fill OOB via direct STS)
// A-style: dst[m][k] (stride 33), global row-major [r][k], k contiguous.
// ---------------------------------------------------------------------------
__device__ __forceinline__ void loadA(float* dst, const float* __restrict__ g,
                                      int ld, int r0, int rmax, int k0,
                                      int kmax, int tid) {
    const int kk = tid & 31;
    const int mb = tid >> 5;
    const bool kin = (k0 + kk) < kmax;
    const float* gp = g + (size_t)r0 * ld + k0 + kk;
#pragma unroll
    for (int i = 0; i < 16; i++) {
        int m = mb + (i << 3);
        float* s = dst + m * 33 + kk;
        if (kin && (r0 + m) < rmax) cp4(s, gp + (size_t)m * ld);
        else *s = 0.0f;
    }
}

// B-style (NN): dst[k][n] (stride 132), global row-major [k][n], n contiguous.
__device__ __forceinline__ void loadB(float* dst, const float* __restrict__ g,
                                      int ld, int n0, int nmax, int k0,
                                      int kmax, int tid) {
    const int nn = tid & 127;
    const int kb = tid >> 7;  // 0..1
    const bool nin = (n0 + nn) < nmax;
    const float* gp = g + (size_t)k0 * ld + n0 + nn;
#pragma unroll
    for (int i = 0; i < 16; i++) {
        int k = kb + (i << 1);
        float* s = dst + k * 132 + nn;
        if (nin && (k0 + k) < kmax) cp4(s, gp + (size_t)k * ld);
        else *s = 0.0f;
    }
}

// ---------------------------------------------------------------------------
// Generic NT/NN tf32 GEMM: C = epi( sum_k A[m,k] * Bop[k,n] )
//  TRANSB=true : B global is [n][k] (k contiguous)   -> NT
//  TRANSB=false: B global is [k][n] (n contiguous)   -> NN
//  MODE 0: C = acc
//  MODE 1: C = acc - u[row] v[col]
//  MODE 2: C = E[idx] + acc * INV_N
// CTA tile 128x128, BK=32, 256 thr, warp tile 32x64.
// ---------------------------------------------------------------------------
#define BUF_F 4224  // floats per buffer (128*33 == 32*132)
#define SMEM_BYTES (4 * BUF_F * 4)

template <int MODE, bool TRANSB>
__global__ void __launch_bounds__(256)
k_gemm(const float* __restrict__ A, size_t sA, int lda,
       const float* __restrict__ B, size_t sB, int ldb,
       float* __restrict__ C, size_t sC, int ldc,
       int M, int N, int K, const float* __restrict__ E) {
    extern __shared__ float sm[];
    float* As = sm;               // 2 buffers
    float* Bs = sm + 2 * BUF_F;   // 2 buffers

    const int tid = threadIdx.x;
    const int b = blockIdx.z;
    const int m0 = blockIdx.y * 128, n0 = blockIdx.x * 128;
    const float* Ab = A + (size_t)b * sA;
    const float* Bb = B + (size_t)b * sB;
    float* Cb = C + (size_t)b * sC;

    const int lane = tid & 31, wid = tid >> 5;
    const int wm = (wid & 3) * 32;   // warp m offset
    const int wn = (wid >> 2) * 64;  // warp n offset
    const int g = lane >> 2, tg = lane & 3;

    float acc[2][8][4];
#pragma unroll
    for (int i = 0; i < 2; i++)
#pragma unroll
        for (int j = 0; j < 8; j++)
#pragma unroll
            for (int r = 0; r < 4; r++) acc[i][j][r] = 0.0f;

    const int nc = (K + 31) >> 5;

    loadA(As, Ab, lda, m0, M, 0, K, tid);
    if (TRANSB) loadA(Bs, Bb, ldb, n0, N, 0, K, tid);
    else        loadB(Bs, Bb, ldb, n0, N, 0, K, tid);
    CP_COMMIT();

    for (int c = 0; c < nc; c++) {
        CP_WAIT0();
        __syncthreads();
        if (c + 1 < nc) {
            const int k0 = (c + 1) << 5;
            const int nb = (c + 1) & 1;
            loadA(As + nb * BUF_F, Ab, lda, m0, M, k0, K, tid);
            if (TRANSB) loadA(Bs + nb * BUF_F, Bb, ldb, n0, N, k0, K, tid);
            else        loadB(Bs + nb * BUF_F, Bb, ldb, n0, N, k0, K, tid);
            CP_COMMIT();
        }
        const float* As_ = As + (c & 1) * BUF_F;
        const float* Bs_ = Bs + (c & 1) * BUF_F;
#pragma unroll
        for (int ks = 0; ks < 4; ks++) {
            const int k = ks * 8;
            uint32_t a[2][4], bf[8][2];
#pragma unroll
            for (int mt = 0; mt < 2; mt++) {
                const int r = wm + mt * 16 + g;
                a[mt][0] = __float_as_uint(As_[r * 33 + k + tg]);
                a[mt][1] = __float_as_uint(As_[(r + 8) * 33 + k + tg]);
                a[mt][2] = __float_as_uint(As_[r * 33 + k + tg + 4]);
                a[mt][3] = __float_as_uint(As_[(r + 8) * 33 + k + tg + 4]);
            }
#pragma unroll
            for (int nt = 0; nt < 8; nt++) {
                const int cn = wn + nt * 8 + g;
                if (TRANSB) {
                    bf[nt][0] = __float_as_uint(Bs_[cn * 33 + k + tg]);
                    bf[nt][1] = __float_as_uint(Bs_[cn * 33 + k + tg + 4]);
                } else {
                    bf[nt][0] = __float_as_uint(Bs_[(k + tg) * 132 + cn]);
                    bf[nt][1] = __float_as_uint(Bs_[(k + tg + 4) * 132 + cn]);
                }
            }
#pragma unroll
            for (int mt = 0; mt < 2; mt++)
#pragma unroll
                for (int nt = 0; nt < 8; nt++) mma8(acc[mt][nt], a[mt], bf[nt]);
        }
        __syncthreads();
    }

    // epilogue (direct from accumulators)
#pragma unroll
    for (int mt = 0; mt < 2; mt++) {
        const int row0 = m0 + wm + mt * 16 + g;
#pragma unroll
        for (int half = 0; half < 2; half++) {
            const int row = row0 + half * 8;
            if (row >= M) continue;
            float uu = 0.0f;
            if (MODE == 1) uu = g_u[b][row];
#pragma unroll
            for (int nt = 0; nt < 8; nt++) {
                const int col = n0 + wn + nt * 8 + tg * 2;
                const float v0 = acc[mt][nt][half * 2 + 0];
                const float v1 = acc[mt][nt][half * 2 + 1];
                const size_t idx = (size_t)row * ldc + col;
                if (MODE == 0) {
                    if (col < N) Cb[idx] = v0;
                    if (col + 1 < N) Cb[idx + 1] = v1;
                } else if (MODE == 1) {
                    if (col < N) Cb[idx] = v0 - uu * g_v[b][col];
                    if (col + 1 < N) Cb[idx + 1] = v1 - uu * g_v[b][col + 1];
                } else {
                    const float* Eb = E + (size_t)b * sC;
                    if (col < N) Cb[idx] = Eb[idx] + v0 * INV_N;
                    if (col + 1 < N) Cb[idx + 1] = Eb[idx + 1] + v1 * INV_N;
                }
            }
        }
    }
}

// ---------------------------------------------------------------------------
// u_b = P h_n,  v_b = Q^T h_n   (exact fp32, tiny)
// ---------------------------------------------------------------------------
__global__ void k_uv(const float* __restrict__ H, const float* __restrict__ P,
                     const float* __restrict__ Q) {
    const int b = blockIdx.x;
    const float* __restrict__ Hb = H + (size_t)b * RDIM * NCOL;
    __shared__ float hn[RDIM];
    for (int e = threadIdx.x; e < RDIM; e += blockDim.x)
        hn[e] = Hb[(size_t)e * NCOL + (NCOL - 1)];
    __syncthreads();
    for (int i = threadIdx.x; i < RDIM; i += blockDim.x) {
        float su = 0.0f, sv = 0.0f;
        for (int e = 0; e < RDIM; e++) {
            su += P[i * RDIM + e] * hn[e];
            sv += hn[e] * Q[e * RDIM + i];
        }
        g_u[b][i] = su;
        g_v[b][i] = sv;
    }
}

// ---------------------------------------------------------------------------
extern "C" void kernel_launch(void* const* d_in, const int* in_sizes, int n_in,
                              void* d_out, int out_size) {
    const float* H = (const float*)d_in[0];
    const float* P = (const float*)d_in[1];
    const float* Q = (const float*)d_in[2];
    float* out = (float*)d_out;

    cudaFuncSetAttribute(k_gemm<0, true>,
                         cudaFuncAttributeMaxDynamicSharedMemorySize, SMEM_BYTES);
    cudaFuncSetAttribute(k_gemm<0, false>,
                         cudaFuncAttributeMaxDynamicSharedMemorySize, SMEM_BYTES);
    cudaFuncSetAttribute(k_gemm<1, false>,
                         cudaFuncAttributeMaxDynamicSharedMemorySize, SMEM_BYTES);
    cudaFuncSetAttribute(k_gemm<2, false>,
                         cudaFuncAttributeMaxDynamicSharedMemorySize, SMEM_BYTES);

    float *Gm, *Tm, *Wm;
    cudaGetSymbolAddress((void**)&Gm, g_G);
    cudaGetSymbolAddress((void**)&Tm, g_T);
    cudaGetSymbolAddress((void**)&Wm, g_W);

    const size_t HB = (size_t)RDIM * NCOL;
    const size_t GB = (size_t)RDIM * RDIM;

    k_uv<<<NBAT, 288>>>(H, P, Q);

    // G = H H^T : M=N=257, K=2049  (NT)
    k_gemm<0, true><<<dim3(3, 3, NBAT), 256, SMEM_BYTES>>>(
        H, HB, NCOL, H, HB, NCOL, Gm, GB, RDIM, RDIM, RDIM, NCOL, nullptr);
    // T = G Q : M=N=K=257  (NN)
    k_gemm<0, false><<<dim3(3, 3, NBAT), 256, SMEM_BYTES>>>(
        Gm, GB, RDIM, Q, 0, RDIM, Tm, GB, RDIM, RDIM, RDIM, RDIM, nullptr);
    // W = P T - u v^T : M=N=K=257  (NN, rank-1 fused)
    k_gemm<1, false><<<dim3(3, 3, NBAT), 256, SMEM_BYTES>>>(
        P, 0, RDIM, Tm, GB, RDIM, Wm, GB, RDIM, RDIM, RDIM, RDIM, nullptr);
    // out = H + (W H)/n : M=257, N=2049, K=257  (NN, residual fused)
    k_gemm<2, false><<<dim3(17, 3, NBAT), 256, SMEM_BYTES>>>(
        Wm, GB, RDIM, H, HB, NCOL, out, HB, NCOL, RDIM, NCOL, RDIM, H);
}